// round 12
// baseline (speedup 1.0000x reference)
#include <cuda_runtime.h>
#include <cuda_fp16.h>
#include <math.h>

#define NN   50000
#define EE   1600000
#define ETOT (EE+NN)
#define IND  64
#define HID  128
#define NH   4
#define HD   32
#define OUTD 64
#define EPS  1e-5f

#define SCAN_B 128   // phase-1 blocks
#define SCAN_T 256   // phase-1 threads/block (each thread: 2 counts)

// ---------------- scratch (device globals; no allocation allowed) ----------
__device__ __align__(16) float    g_h  [NN*HID];   // activations between stages
__device__ __align__(16) __half   g_hWh[NN*HID];   // h @ W in fp16 (agg gather)
__device__ __align__(16) float    g_agg[NN*HID];   // normalized aggregation (layer2)
__device__ __align__(16) float4   g_es [NN];       // per-node per-head src score
__device__ __align__(16) float4   g_ed [NN];       // per-node per-head dst score
__device__ int g_cnt   [NN];                       // CSR: per-dst degree
__device__ int g_rowptr[NN+1];                     // CSR: row pointers
__device__ int g_pos   [NN];                       // CSR: scatter cursors
__device__ int g_csrc  [ETOT];                     // CSR: src id per slot
__device__ int g_tpre  [SCAN_B*SCAN_T];            // scan: per-thread prefix
__device__ int g_bsum  [SCAN_B];                   // scan: block totals
__device__ int g_bbase [SCAN_B];                   // scan: block bases

// ---------------- helpers --------------------------------------------------
__device__ __forceinline__ float gelu_f(float x){
  return 0.5f*x*(1.f+tanhf(0.7978845608028654f*(x+0.044715f*x*x*x)));
}
__device__ __forceinline__ float lrelu(float x){ return x>0.f ? x : 0.2f*x; }
__device__ __forceinline__ int clampN(int v){
  return v<0?0:(v>=NN?NN-1:v);
}

// ---------------- stage 1: h = gelu(LN(x @ w_in + b_in)) -------------------
__global__ void __launch_bounds__(128) k_in(
    const float* __restrict__ x, const float* __restrict__ w,
    const float* __restrict__ b, const float* __restrict__ gam,
    const float* __restrict__ bet)
{
  __shared__ float ws[IND*HID];   // 32 KB
  __shared__ float xs[16*IND];    //  4 KB
  __shared__ float hb[16*HID];    //  8 KB
  const int t = threadIdx.x;
  const int row0 = blockIdx.x*16;   // 50000/16 = 3125 exact

  for(int i=t;i<IND*HID;i+=128) ws[i]=w[i];
  for(int i=t;i<16*IND;i+=128)  xs[i]=x[row0*IND+i];
  __syncthreads();

  const int cg=t&31, rg=t>>5;
  float4 bb=*(const float4*)&b[4*cg];
  float acc[4][4];
  #pragma unroll
  for(int r=0;r<4;r++){acc[r][0]=bb.x;acc[r][1]=bb.y;acc[r][2]=bb.z;acc[r][3]=bb.w;}

  for(int k=0;k<IND;k++){
    float4 wv=*(float4*)&ws[k*HID+4*cg];
    #pragma unroll
    for(int r=0;r<4;r++){
      float hv=xs[(rg*4+r)*IND+k];
      acc[r][0]+=hv*wv.x; acc[r][1]+=hv*wv.y; acc[r][2]+=hv*wv.z; acc[r][3]+=hv*wv.w;
    }
  }
  #pragma unroll
  for(int r=0;r<4;r++)
    *(float4*)&hb[(rg*4+r)*HID+4*cg]=make_float4(acc[r][0],acc[r][1],acc[r][2],acc[r][3]);
  __syncthreads();

  const int lane=t&31, wid=t>>5;
  float4 gg=*(const float4*)&gam[lane*4];
  float4 b2=*(const float4*)&bet[lane*4];
  for(int r=wid;r<16;r+=4){
    float4 v=*(float4*)&hb[r*HID+lane*4];
    float s=v.x+v.y+v.z+v.w;
    float q=v.x*v.x+v.y*v.y+v.z*v.z+v.w*v.w;
    #pragma unroll
    for(int o=16;o;o>>=1){
      s+=__shfl_xor_sync(0xffffffffu,s,o);
      q+=__shfl_xor_sync(0xffffffffu,q,o);
    }
    float mu=s*(1.f/HID);
    float rs=rsqrtf(q*(1.f/HID)-mu*mu+EPS);
    v.x=gelu_f((v.x-mu)*rs*gg.x+b2.x);
    v.y=gelu_f((v.y-mu)*rs*gg.y+b2.y);
    v.z=gelu_f((v.z-mu)*rs*gg.z+b2.z);
    v.w=gelu_f((v.w-mu)*rs*gg.w+b2.w);
    *(float4*)&g_h[(row0+r)*HID+lane*4]=v;
  }
}

// ---------------- stage 2: hW(fp16) = h @ W ; e_src/e_dst ------------------
// 256 threads, 64 rows/block, W streamed in two 64-row k-chunks.
__global__ void __launch_bounds__(256) k_hw(
    const float* __restrict__ W, const float* __restrict__ asrc,
    const float* __restrict__ adst)
{
  extern __shared__ float sm[];
  float* Wc  = sm;                 // 64x128 chunk of W (32 KB)
  float* hs  = sm + 64*HID;        // 64x128 inputs   (32 KB)
  float* hwb = hs + 64*HID;        // 64x128 outputs  (32 KB)
  const int t = threadIdx.x;
  const int row0 = blockIdx.x*64;
  const int nrows = min(64, NN-row0);

  for(int i=t;i<nrows*HID;i+=256) hs[i]=g_h[row0*HID+i];
  for(int i=nrows*HID+t;i<64*HID;i+=256) hs[i]=0.f;

  const int cg=t&31, rg=t>>5;      // cols 4*cg.., rows rg*8..rg*8+7
  float acc[8][4];
  #pragma unroll
  for(int r=0;r<8;r++){acc[r][0]=0;acc[r][1]=0;acc[r][2]=0;acc[r][3]=0;}

  for(int kc=0;kc<2;kc++){
    __syncthreads();
    for(int i=t;i<64*HID;i+=256) Wc[i]=W[kc*64*HID+i];
    __syncthreads();
    #pragma unroll 4
    for(int k=0;k<64;k++){
      float4 wv=*(float4*)&Wc[k*HID+4*cg];
      #pragma unroll
      for(int r=0;r<8;r++){
        float hv=hs[(rg*8+r)*HID+kc*64+k];
        acc[r][0]+=hv*wv.x; acc[r][1]+=hv*wv.y; acc[r][2]+=hv*wv.z; acc[r][3]+=hv*wv.w;
      }
    }
  }
  __syncthreads();
  #pragma unroll
  for(int r=0;r<8;r++)
    *(float4*)&hwb[(rg*8+r)*HID+4*cg]=make_float4(acc[r][0],acc[r][1],acc[r][2],acc[r][3]);
  __syncthreads();

  // fp16 copy out (only consumer is k_agg): half2 vector stores
  for(int i=t;i<nrows*(HID/2);i+=256){
    float2 f2=*(const float2*)&hwb[i*2];
    *(__half2*)&g_hWh[row0*HID+i*2]=__floats2half2_rn(f2.x,f2.y);
  }

  // attention scores: warp per row (8 warps cycle over 64 rows)
  const int lane=t&31, wid=t>>5;
  for(int r=wid;r<nrows;r+=8){
    float ps[NH], pd[NH];
    #pragma unroll
    for(int h=0;h<NH;h++){
      float v=hwb[r*HID+h*HD+lane];
      ps[h]=v*asrc[h*HD+lane];
      pd[h]=v*adst[h*HD+lane];
    }
    #pragma unroll
    for(int o=16;o;o>>=1){
      #pragma unroll
      for(int h=0;h<NH;h++){
        ps[h]+=__shfl_xor_sync(0xffffffffu,ps[h],o);
        pd[h]+=__shfl_xor_sync(0xffffffffu,pd[h],o);
      }
    }
    if(lane==0){
      g_es[row0+r]=make_float4(ps[0],ps[1],ps[2],ps[3]);
      g_ed[row0+r]=make_float4(pd[0],pd[1],pd[2],pd[3]);
    }
  }
}

// ---------------- CSR build (once; reused by both layers) ------------------
__global__ void k_zero_cnt(){
  int i=blockIdx.x*blockDim.x+threadIdx.x;
  if(i<NN) g_cnt[i]=0;
}
__global__ void k_hist(const int* __restrict__ ei){
  int i=blockIdx.x*blockDim.x+threadIdx.x;
  if(i>=ETOT) return;
  int d = (i<EE)? clampN(ei[EE+i]) : i-EE;
  atomicAdd(&g_cnt[d],1);
}
// 3-phase device-wide exclusive scan of g_cnt -> g_rowptr/g_pos
__global__ void __launch_bounds__(SCAN_T) k_scan1(){
  __shared__ int sh[SCAN_T];
  const int t=threadIdx.x, b=blockIdx.x;
  const int g=b*SCAN_T+t;
  const int i0=g*2;
  int c0=(i0<NN)? g_cnt[i0]:0;
  int c1=(i0+1<NN)? g_cnt[i0+1]:0;
  sh[t]=c0+c1; __syncthreads();
  for(int off=1;off<SCAN_T;off<<=1){
    int v=(t>=off)? sh[t-off]:0; __syncthreads();
    sh[t]+=v; __syncthreads();
  }
  g_tpre[g]=(t==0)?0:sh[t-1];
  if(t==SCAN_T-1) g_bsum[b]=sh[SCAN_T-1];
}
__global__ void __launch_bounds__(SCAN_B) k_scan2(){
  __shared__ int sh[SCAN_B];
  const int t=threadIdx.x;
  sh[t]=g_bsum[t]; __syncthreads();
  for(int off=1;off<SCAN_B;off<<=1){
    int v=(t>=off)? sh[t-off]:0; __syncthreads();
    sh[t]+=v; __syncthreads();
  }
  g_bbase[t]=(t==0)?0:sh[t-1];
}
__global__ void __launch_bounds__(SCAN_T) k_scan3(){
  const int t=threadIdx.x, b=blockIdx.x;
  const int g=b*SCAN_T+t;
  const int i0=g*2;
  int base=g_bbase[b]+g_tpre[g];
  if(i0<NN){
    g_rowptr[i0]=base; g_pos[i0]=base;
    int nb=base+g_cnt[i0];
    if(i0+1<NN){ g_rowptr[i0+1]=nb; g_pos[i0+1]=nb; }
  }
  if(g==0) g_rowptr[NN]=ETOT;
}
__global__ void k_scatter(const int* __restrict__ ei){
  int i=blockIdx.x*blockDim.x+threadIdx.x;
  if(i>=ETOT) return;
  int s,d;
  if(i<EE){ s=clampN(ei[i]); d=clampN(ei[EE+i]); } else { s=d=i-EE; }
  int p=atomicAdd(&g_pos[d],1);
  g_csrc[p]=s;
}

// ---------------- fused aggregation: warp per dst node ---------------------
// acc = sum_e exp(lrelu(es[s]+ed[d])) * hW_fp16[s]; den = sum_e w; fp32 accum.
// 4-way unrolled gather (uint2 = 4 halves per lane). FUSE_LN: +b+LN+gelu.
template<bool FUSE_LN>
__global__ void __launch_bounds__(256) k_agg(
    const float* __restrict__ bg, const float* __restrict__ gam,
    const float* __restrict__ bet)
{
  int node=(blockIdx.x*blockDim.x+threadIdx.x)>>5;
  int lane=threadIdx.x&31;
  if(node>=NN) return;
  const int h=lane>>3;
  const int beg=g_rowptr[node], end=g_rowptr[node+1];
  const float edv=((const float*)g_ed)[node*4+h];
  const __half2* hw2=(const __half2*)g_hWh;
  const int col2=lane*2;           // half2 column index (lane*4 halves)

  float4 acc=make_float4(0.f,0.f,0.f,0.f);
  float den=0.f;
  int j=beg;
  for(; j+3<end; j+=4){
    int s0=g_csrc[j],   s1=g_csrc[j+1];
    int s2=g_csrc[j+2], s3=g_csrc[j+3];
    float e0=((const float*)g_es)[s0*4+h];
    float e1=((const float*)g_es)[s1*4+h];
    float e2=((const float*)g_es)[s2*4+h];
    float e3=((const float*)g_es)[s3*4+h];
    __half2 a0=hw2[s0*(HID/2)+col2], b0=hw2[s0*(HID/2)+col2+1];
    __half2 a1=hw2[s1*(HID/2)+col2], b1=hw2[s1*(HID/2)+col2+1];
    __half2 a2=hw2[s2*(HID/2)+col2], b2=hw2[s2*(HID/2)+col2+1];
    __half2 a3=hw2[s3*(HID/2)+col2], b3=hw2[s3*(HID/2)+col2+1];
    float w0=__expf(lrelu(e0+edv));
    float w1=__expf(lrelu(e1+edv));
    float w2=__expf(lrelu(e2+edv));
    float w3=__expf(lrelu(e3+edv));
    float2 f;
    f=__half22float2(a0); acc.x+=w0*f.x; acc.y+=w0*f.y;
    f=__half22float2(b0); acc.z+=w0*f.x; acc.w+=w0*f.y;
    f=__half22float2(a1); acc.x+=w1*f.x; acc.y+=w1*f.y;
    f=__half22float2(b1); acc.z+=w1*f.x; acc.w+=w1*f.y;
    f=__half22float2(a2); acc.x+=w2*f.x; acc.y+=w2*f.y;
    f=__half22float2(b2); acc.z+=w2*f.x; acc.w+=w2*f.y;
    f=__half22float2(a3); acc.x+=w3*f.x; acc.y+=w3*f.y;
    f=__half22float2(b3); acc.z+=w3*f.x; acc.w+=w3*f.y;
    den+=(w0+w1)+(w2+w3);
  }
  for(; j<end; j++){
    int s=g_csrc[j];
    float w=__expf(lrelu(((const float*)g_es)[s*4+h]+edv));
    __half2 a=hw2[s*(HID/2)+col2], b=hw2[s*(HID/2)+col2+1];
    float2 f;
    f=__half22float2(a); acc.x+=w*f.x; acc.y+=w*f.y;
    f=__half22float2(b); acc.z+=w*f.x; acc.w+=w*f.y;
    den+=w;
  }
  float inv=1.f/den;
  float4 v;
  v.x=acc.x*inv; v.y=acc.y*inv; v.z=acc.z*inv; v.w=acc.w*inv;

  if(FUSE_LN){
    float4 b4=*(const float4*)&bg[lane*4];
    v.x+=b4.x; v.y+=b4.y; v.z+=b4.z; v.w+=b4.w;
    float s=v.x+v.y+v.z+v.w;
    float q=v.x*v.x+v.y*v.y+v.z*v.z+v.w*v.w;
    #pragma unroll
    for(int o=16;o;o>>=1){
      s+=__shfl_xor_sync(0xffffffffu,s,o);
      q+=__shfl_xor_sync(0xffffffffu,q,o);
    }
    float mu=s*(1.f/HID);
    float rs=rsqrtf(q*(1.f/HID)-mu*mu+EPS);
    float4 gg=*(const float4*)&gam[lane*4];
    float4 b2=*(const float4*)&bet[lane*4];
    v.x=gelu_f((v.x-mu)*rs*gg.x+b2.x);
    v.y=gelu_f((v.y-mu)*rs*gg.y+b2.y);
    v.z=gelu_f((v.z-mu)*rs*gg.z+b2.z);
    v.w=gelu_f((v.w-mu)*rs*gg.w+b2.w);
    *(float4*)&g_h[node*HID+lane*4]=v;
  }else{
    *(float4*)&g_agg[node*HID+lane*4]=v;
  }
}

// ---------------- final: out = (agg + bg2) @ w_out + b_out -----------------
__global__ void __launch_bounds__(128) k_out(
    const float* __restrict__ bg, const float* __restrict__ w,
    const float* __restrict__ bo, float* __restrict__ out)
{
  __shared__ float ws[HID*OUTD];  // 32 KB
  __shared__ float hs[32*HID];    // 16 KB
  const int t=threadIdx.x;
  const int row0=blockIdx.x*32;
  const int nrows=min(32, NN-row0);

  for(int i=t;i<HID*OUTD;i+=128) ws[i]=w[i];
  for(int i=t;i<32*HID;i+=128){
    int r=i>>7, c=i&127;
    hs[i]=(r<nrows)? g_agg[row0*HID+i]+bg[c] : 0.f;
  }
  __syncthreads();

  const int cg=t&15, rg=t>>4;
  float acc[4][4];
  #pragma unroll
  for(int r=0;r<4;r++){acc[r][0]=0;acc[r][1]=0;acc[r][2]=0;acc[r][3]=0;}

  for(int k=0;k<HID;k++){
    float4 wv=*(float4*)&ws[k*OUTD+4*cg];
    #pragma unroll
    for(int r=0;r<4;r++){
      float hv=hs[(rg*4+r)*HID+k];
      acc[r][0]+=hv*wv.x; acc[r][1]+=hv*wv.y; acc[r][2]+=hv*wv.z; acc[r][3]+=hv*wv.w;
    }
  }
  float4 b4=*(const float4*)&bo[4*cg];
  #pragma unroll
  for(int r=0;r<4;r++){
    int row=row0+rg*4+r;
    if(row<NN)
      *(float4*)&out[row*OUTD+4*cg]=
        make_float4(acc[r][0]+b4.x,acc[r][1]+b4.y,acc[r][2]+b4.z,acc[r][3]+b4.w);
  }
}

// ---------------- launch ----------------------------------------------------
extern "C" void kernel_launch(void* const* d_in, const int* in_sizes, int n_in,
                              void* d_out, int out_size)
{
  const float* x    =(const float*)d_in[0];
  const int*   ei   =(const int*)d_in[1];
  const float* w_in =(const float*)d_in[2];
  const float* b_in =(const float*)d_in[3];
  const float* g1   =(const float*)d_in[4];
  const float* be1  =(const float*)d_in[5];
  const float* W1   =(const float*)d_in[6];
  const float* as1  =(const float*)d_in[7];
  const float* ad1  =(const float*)d_in[8];
  const float* bg1  =(const float*)d_in[9];
  const float* g2   =(const float*)d_in[10];
  const float* be2  =(const float*)d_in[11];
  const float* W2   =(const float*)d_in[12];
  const float* as2  =(const float*)d_in[13];
  const float* ad2  =(const float*)d_in[14];
  const float* bg2  =(const float*)d_in[15];
  const float* w_out=(const float*)d_in[16];
  const float* b_out=(const float*)d_in[17];
  float* out=(float*)d_out;

  const size_t shw=(64*HID*3)*sizeof(float); // 96 KB
  cudaFuncSetAttribute(k_hw, cudaFuncAttributeMaxDynamicSharedMemorySize,(int)shw);

  const int gHW  =(NN+63)/64;
  const int gO   =(NN+31)/32;
  const int gE   =(ETOT+255)/256;
  const int gN   =(NN+255)/256;
  const int gAGG =(NN*32+255)/256;   // warp per node

  // dense stage 1 + CSR build (CSR independent of features)
  k_in<<<NN/16,128>>>(x,w_in,b_in,g1,be1);
  k_zero_cnt<<<gN,256>>>();
  k_hist<<<gE,256>>>(ei);
  k_scan1<<<SCAN_B,SCAN_T>>>();
  k_scan2<<<1,SCAN_B>>>();
  k_scan3<<<SCAN_B,SCAN_T>>>();
  k_scatter<<<gE,256>>>(ei);

  // ---- GAT layer 1 (fused agg + LN + gelu)
  k_hw<<<gHW,256,shw>>>(W1,as1,ad1);
  k_agg<true><<<gAGG,256>>>(bg1,g2,be2);

  // ---- GAT layer 2
  k_hw<<<gHW,256,shw>>>(W2,as2,ad2);
  k_agg<false><<<gAGG,256>>>(nullptr,nullptr,nullptr);

  k_out<<<gO,128>>>(bg2,w_out,b_out,out);
}

// round 13
// speedup vs baseline: 1.0086x; 1.0086x over previous
#include <cuda_runtime.h>
#include <cuda_fp16.h>
#include <math.h>

#define NN   50000
#define EE   1600000
#define ETOT (EE+NN)
#define IND  64
#define HID  128
#define NH   4
#define HD   32
#define OUTD 64
#define EPS  1e-5f

#define SCAN_B 128   // phase-1 blocks
#define SCAN_T 256   // phase-1 threads/block (each thread: 2 counts)

// ---------------- scratch (device globals; no allocation allowed) ----------
__device__ __align__(16) float    g_h  [NN*HID];   // activations between stages
__device__ __align__(16) __half   g_hWh[NN*HID];   // h @ W in fp16 (agg gather)
__device__ __align__(16) float    g_agg[NN*HID];   // normalized aggregation (layer2)
__device__ __align__(16) float4   g_es [NN];       // per-node per-head src score
__device__ __align__(16) float4   g_ed [NN];       // per-node per-head dst score
__device__ int g_cnt   [NN];                       // CSR: per-dst degree
__device__ int g_rowptr[NN+1];                     // CSR: row pointers
__device__ int g_pos   [NN];                       // CSR: scatter cursors
__device__ int g_csrc  [ETOT];                     // CSR: src id per slot
__device__ int g_tpre  [SCAN_B*SCAN_T];            // scan: per-thread prefix
__device__ int g_bsum  [SCAN_B];                   // scan: block totals
__device__ int g_bbase [SCAN_B];                   // scan: block bases

// ---------------- helpers --------------------------------------------------
__device__ __forceinline__ float gelu_f(float x){
  return 0.5f*x*(1.f+tanhf(0.7978845608028654f*(x+0.044715f*x*x*x)));
}
__device__ __forceinline__ float lrelu(float x){ return x>0.f ? x : 0.2f*x; }
__device__ __forceinline__ int clampN(int v){
  return v<0?0:(v>=NN?NN-1:v);
}
// unpack 4 halves (as uint2) and accumulate with weight w
__device__ __forceinline__ void acc4h(float4& acc, uint2 p, float w){
  __half2 lo=*reinterpret_cast<__half2*>(&p.x);
  __half2 hi=*reinterpret_cast<__half2*>(&p.y);
  float2 f0=__half22float2(lo), f1=__half22float2(hi);
  acc.x+=w*f0.x; acc.y+=w*f0.y; acc.z+=w*f1.x; acc.w+=w*f1.y;
}

// ---------------- stage 1: h = gelu(LN(x @ w_in + b_in)) -------------------
__global__ void __launch_bounds__(128) k_in(
    const float* __restrict__ x, const float* __restrict__ w,
    const float* __restrict__ b, const float* __restrict__ gam,
    const float* __restrict__ bet)
{
  __shared__ float ws[IND*HID];   // 32 KB
  __shared__ float xs[16*IND];    //  4 KB
  __shared__ float hb[16*HID];    //  8 KB
  const int t = threadIdx.x;
  const int row0 = blockIdx.x*16;   // 50000/16 = 3125 exact

  for(int i=t;i<IND*HID;i+=128) ws[i]=w[i];
  for(int i=t;i<16*IND;i+=128)  xs[i]=x[row0*IND+i];
  __syncthreads();

  const int cg=t&31, rg=t>>5;
  float4 bb=*(const float4*)&b[4*cg];
  float acc[4][4];
  #pragma unroll
  for(int r=0;r<4;r++){acc[r][0]=bb.x;acc[r][1]=bb.y;acc[r][2]=bb.z;acc[r][3]=bb.w;}

  for(int k=0;k<IND;k++){
    float4 wv=*(float4*)&ws[k*HID+4*cg];
    #pragma unroll
    for(int r=0;r<4;r++){
      float hv=xs[(rg*4+r)*IND+k];
      acc[r][0]+=hv*wv.x; acc[r][1]+=hv*wv.y; acc[r][2]+=hv*wv.z; acc[r][3]+=hv*wv.w;
    }
  }
  #pragma unroll
  for(int r=0;r<4;r++)
    *(float4*)&hb[(rg*4+r)*HID+4*cg]=make_float4(acc[r][0],acc[r][1],acc[r][2],acc[r][3]);
  __syncthreads();

  const int lane=t&31, wid=t>>5;
  float4 gg=*(const float4*)&gam[lane*4];
  float4 b2=*(const float4*)&bet[lane*4];
  for(int r=wid;r<16;r+=4){
    float4 v=*(float4*)&hb[r*HID+lane*4];
    float s=v.x+v.y+v.z+v.w;
    float q=v.x*v.x+v.y*v.y+v.z*v.z+v.w*v.w;
    #pragma unroll
    for(int o=16;o;o>>=1){
      s+=__shfl_xor_sync(0xffffffffu,s,o);
      q+=__shfl_xor_sync(0xffffffffu,q,o);
    }
    float mu=s*(1.f/HID);
    float rs=rsqrtf(q*(1.f/HID)-mu*mu+EPS);
    v.x=gelu_f((v.x-mu)*rs*gg.x+b2.x);
    v.y=gelu_f((v.y-mu)*rs*gg.y+b2.y);
    v.z=gelu_f((v.z-mu)*rs*gg.z+b2.z);
    v.w=gelu_f((v.w-mu)*rs*gg.w+b2.w);
    *(float4*)&g_h[(row0+r)*HID+lane*4]=v;
  }
}

// ---------------- stage 2: hW(fp16) = h @ W ; e_src/e_dst ------------------
// 256 threads, 64 rows/block, W streamed in two 64-row k-chunks.
__global__ void __launch_bounds__(256) k_hw(
    const float* __restrict__ W, const float* __restrict__ asrc,
    const float* __restrict__ adst)
{
  extern __shared__ float sm[];
  float* Wc  = sm;                 // 64x128 chunk of W (32 KB)
  float* hs  = sm + 64*HID;        // 64x128 inputs   (32 KB)
  float* hwb = hs + 64*HID;        // 64x128 outputs  (32 KB)
  const int t = threadIdx.x;
  const int row0 = blockIdx.x*64;
  const int nrows = min(64, NN-row0);

  for(int i=t;i<nrows*HID;i+=256) hs[i]=g_h[row0*HID+i];
  for(int i=nrows*HID+t;i<64*HID;i+=256) hs[i]=0.f;

  const int cg=t&31, rg=t>>5;      // cols 4*cg.., rows rg*8..rg*8+7
  float acc[8][4];
  #pragma unroll
  for(int r=0;r<8;r++){acc[r][0]=0;acc[r][1]=0;acc[r][2]=0;acc[r][3]=0;}

  for(int kc=0;kc<2;kc++){
    __syncthreads();
    for(int i=t;i<64*HID;i+=256) Wc[i]=W[kc*64*HID+i];
    __syncthreads();
    #pragma unroll 4
    for(int k=0;k<64;k++){
      float4 wv=*(float4*)&Wc[k*HID+4*cg];
      #pragma unroll
      for(int r=0;r<8;r++){
        float hv=hs[(rg*8+r)*HID+kc*64+k];
        acc[r][0]+=hv*wv.x; acc[r][1]+=hv*wv.y; acc[r][2]+=hv*wv.z; acc[r][3]+=hv*wv.w;
      }
    }
  }
  __syncthreads();
  #pragma unroll
  for(int r=0;r<8;r++)
    *(float4*)&hwb[(rg*8+r)*HID+4*cg]=make_float4(acc[r][0],acc[r][1],acc[r][2],acc[r][3]);
  __syncthreads();

  // fp16 copy out (only consumer is k_agg): half2 vector stores
  for(int i=t;i<nrows*(HID/2);i+=256){
    float2 f2=*(const float2*)&hwb[i*2];
    *(__half2*)&g_hWh[row0*HID+i*2]=__floats2half2_rn(f2.x,f2.y);
  }

  // attention scores: warp per row (8 warps cycle over 64 rows)
  const int lane=t&31, wid=t>>5;
  for(int r=wid;r<nrows;r+=8){
    float ps[NH], pd[NH];
    #pragma unroll
    for(int h=0;h<NH;h++){
      float v=hwb[r*HID+h*HD+lane];
      ps[h]=v*asrc[h*HD+lane];
      pd[h]=v*adst[h*HD+lane];
    }
    #pragma unroll
    for(int o=16;o;o>>=1){
      #pragma unroll
      for(int h=0;h<NH;h++){
        ps[h]+=__shfl_xor_sync(0xffffffffu,ps[h],o);
        pd[h]+=__shfl_xor_sync(0xffffffffu,pd[h],o);
      }
    }
    if(lane==0){
      g_es[row0+r]=make_float4(ps[0],ps[1],ps[2],ps[3]);
      g_ed[row0+r]=make_float4(pd[0],pd[1],pd[2],pd[3]);
    }
  }
}

// ---------------- CSR build (once; reused by both layers) ------------------
__global__ void k_zero_cnt(){
  int i=blockIdx.x*blockDim.x+threadIdx.x;
  if(i<NN) g_cnt[i]=0;
}
__global__ void k_hist(const int* __restrict__ ei){
  int i=blockIdx.x*blockDim.x+threadIdx.x;
  if(i>=ETOT) return;
  int d = (i<EE)? clampN(ei[EE+i]) : i-EE;
  atomicAdd(&g_cnt[d],1);
}
// 3-phase device-wide exclusive scan of g_cnt -> g_rowptr/g_pos
__global__ void __launch_bounds__(SCAN_T) k_scan1(){
  __shared__ int sh[SCAN_T];
  const int t=threadIdx.x, b=blockIdx.x;
  const int g=b*SCAN_T+t;
  const int i0=g*2;
  int c0=(i0<NN)? g_cnt[i0]:0;
  int c1=(i0+1<NN)? g_cnt[i0+1]:0;
  sh[t]=c0+c1; __syncthreads();
  for(int off=1;off<SCAN_T;off<<=1){
    int v=(t>=off)? sh[t-off]:0; __syncthreads();
    sh[t]+=v; __syncthreads();
  }
  g_tpre[g]=(t==0)?0:sh[t-1];
  if(t==SCAN_T-1) g_bsum[b]=sh[SCAN_T-1];
}
__global__ void __launch_bounds__(SCAN_B) k_scan2(){
  __shared__ int sh[SCAN_B];
  const int t=threadIdx.x;
  sh[t]=g_bsum[t]; __syncthreads();
  for(int off=1;off<SCAN_B;off<<=1){
    int v=(t>=off)? sh[t-off]:0; __syncthreads();
    sh[t]+=v; __syncthreads();
  }
  g_bbase[t]=(t==0)?0:sh[t-1];
}
__global__ void __launch_bounds__(SCAN_T) k_scan3(){
  const int t=threadIdx.x, b=blockIdx.x;
  const int g=b*SCAN_T+t;
  const int i0=g*2;
  int base=g_bbase[b]+g_tpre[g];
  if(i0<NN){
    g_rowptr[i0]=base; g_pos[i0]=base;
    int nb=base+g_cnt[i0];
    if(i0+1<NN){ g_rowptr[i0+1]=nb; g_pos[i0+1]=nb; }
  }
  if(g==0) g_rowptr[NN]=ETOT;
}
__global__ void k_scatter(const int* __restrict__ ei){
  int i=blockIdx.x*blockDim.x+threadIdx.x;
  if(i>=ETOT) return;
  int s,d;
  if(i<EE){ s=clampN(ei[i]); d=clampN(ei[EE+i]); } else { s=d=i-EE; }
  int p=atomicAdd(&g_pos[d],1);
  g_csrc[p]=s;
}

// ---------------- fused aggregation: warp per dst node ---------------------
// acc = sum_e exp(lrelu(es[s]+ed[d])) * hW_fp16[s]; den = sum_e w; fp32 accum.
// ONE 8-byte LDG per edge-lane (uint2 = 4 halves). 4-way unrolled for MLP.
template<bool FUSE_LN>
__global__ void __launch_bounds__(256) k_agg(
    const float* __restrict__ bg, const float* __restrict__ gam,
    const float* __restrict__ bet)
{
  int node=(blockIdx.x*blockDim.x+threadIdx.x)>>5;
  int lane=threadIdx.x&31;
  if(node>=NN) return;
  const int h=lane>>3;
  const int beg=g_rowptr[node], end=g_rowptr[node+1];
  const float edv=((const float*)g_ed)[node*4+h];
  const uint2* hw4=(const uint2*)g_hWh;     // 4 halves per element
  const int col4=lane;                      // lane*4 halves = lane-th uint2

  float4 acc=make_float4(0.f,0.f,0.f,0.f);
  float den=0.f;
  int j=beg;
  for(; j+3<end; j+=4){
    int s0=g_csrc[j],   s1=g_csrc[j+1];
    int s2=g_csrc[j+2], s3=g_csrc[j+3];
    float e0=((const float*)g_es)[s0*4+h];
    float e1=((const float*)g_es)[s1*4+h];
    float e2=((const float*)g_es)[s2*4+h];
    float e3=((const float*)g_es)[s3*4+h];
    uint2 p0=hw4[s0*(HID/4)+col4];
    uint2 p1=hw4[s1*(HID/4)+col4];
    uint2 p2=hw4[s2*(HID/4)+col4];
    uint2 p3=hw4[s3*(HID/4)+col4];
    float w0=__expf(lrelu(e0+edv));
    float w1=__expf(lrelu(e1+edv));
    float w2=__expf(lrelu(e2+edv));
    float w3=__expf(lrelu(e3+edv));
    acc4h(acc,p0,w0); acc4h(acc,p1,w1); acc4h(acc,p2,w2); acc4h(acc,p3,w3);
    den+=(w0+w1)+(w2+w3);
  }
  for(; j<end; j++){
    int s=g_csrc[j];
    float w=__expf(lrelu(((const float*)g_es)[s*4+h]+edv));
    uint2 p=hw4[s*(HID/4)+col4];
    acc4h(acc,p,w);
    den+=w;
  }
  float inv=1.f/den;
  float4 v;
  v.x=acc.x*inv; v.y=acc.y*inv; v.z=acc.z*inv; v.w=acc.w*inv;

  if(FUSE_LN){
    float4 b4=*(const float4*)&bg[lane*4];
    v.x+=b4.x; v.y+=b4.y; v.z+=b4.z; v.w+=b4.w;
    float s=v.x+v.y+v.z+v.w;
    float q=v.x*v.x+v.y*v.y+v.z*v.z+v.w*v.w;
    #pragma unroll
    for(int o=16;o;o>>=1){
      s+=__shfl_xor_sync(0xffffffffu,s,o);
      q+=__shfl_xor_sync(0xffffffffu,q,o);
    }
    float mu=s*(1.f/HID);
    float rs=rsqrtf(q*(1.f/HID)-mu*mu+EPS);
    float4 gg=*(const float4*)&gam[lane*4];
    float4 b2=*(const float4*)&bet[lane*4];
    v.x=gelu_f((v.x-mu)*rs*gg.x+b2.x);
    v.y=gelu_f((v.y-mu)*rs*gg.y+b2.y);
    v.z=gelu_f((v.z-mu)*rs*gg.z+b2.z);
    v.w=gelu_f((v.w-mu)*rs*gg.w+b2.w);
    *(float4*)&g_h[node*HID+lane*4]=v;
  }else{
    *(float4*)&g_agg[node*HID+lane*4]=v;
  }
}

// ---------------- final: out = (agg + bg2) @ w_out + b_out -----------------
__global__ void __launch_bounds__(128) k_out(
    const float* __restrict__ bg, const float* __restrict__ w,
    const float* __restrict__ bo, float* __restrict__ out)
{
  __shared__ float ws[HID*OUTD];  // 32 KB
  __shared__ float hs[32*HID];    // 16 KB
  const int t=threadIdx.x;
  const int row0=blockIdx.x*32;
  const int nrows=min(32, NN-row0);

  for(int i=t;i<HID*OUTD;i+=128) ws[i]=w[i];
  for(int i=t;i<32*HID;i+=128){
    int r=i>>7, c=i&127;
    hs[i]=(r<nrows)? g_agg[row0*HID+i]+bg[c] : 0.f;
  }
  __syncthreads();

  const int cg=t&15, rg=t>>4;
  float acc[4][4];
  #pragma unroll
  for(int r=0;r<4;r++){acc[r][0]=0;acc[r][1]=0;acc[r][2]=0;acc[r][3]=0;}

  for(int k=0;k<HID;k++){
    float4 wv=*(float4*)&ws[k*OUTD+4*cg];
    #pragma unroll
    for(int r=0;r<4;r++){
      float hv=hs[(rg*4+r)*HID+k];
      acc[r][0]+=hv*wv.x; acc[r][1]+=hv*wv.y; acc[r][2]+=hv*wv.z; acc[r][3]+=hv*wv.w;
    }
  }
  float4 b4=*(const float4*)&bo[4*cg];
  #pragma unroll
  for(int r=0;r<4;r++){
    int row=row0+rg*4+r;
    if(row<NN)
      *(float4*)&out[row*OUTD+4*cg]=
        make_float4(acc[r][0]+b4.x,acc[r][1]+b4.y,acc[r][2]+b4.z,acc[r][3]+b4.w);
  }
}

// ---------------- launch ----------------------------------------------------
extern "C" void kernel_launch(void* const* d_in, const int* in_sizes, int n_in,
                              void* d_out, int out_size)
{
  const float* x    =(const float*)d_in[0];
  const int*   ei   =(const int*)d_in[1];
  const float* w_in =(const float*)d_in[2];
  const float* b_in =(const float*)d_in[3];
  const float* g1   =(const float*)d_in[4];
  const float* be1  =(const float*)d_in[5];
  const float* W1   =(const float*)d_in[6];
  const float* as1  =(const float*)d_in[7];
  const float* ad1  =(const float*)d_in[8];
  const float* bg1  =(const float*)d_in[9];
  const float* g2   =(const float*)d_in[10];
  const float* be2  =(const float*)d_in[11];
  const float* W2   =(const float*)d_in[12];
  const float* as2  =(const float*)d_in[13];
  const float* ad2  =(const float*)d_in[14];
  const float* bg2  =(const float*)d_in[15];
  const float* w_out=(const float*)d_in[16];
  const float* b_out=(const float*)d_in[17];
  float* out=(float*)d_out;

  const size_t shw=(64*HID*3)*sizeof(float); // 96 KB
  cudaFuncSetAttribute(k_hw, cudaFuncAttributeMaxDynamicSharedMemorySize,(int)shw);

  const int gHW  =(NN+63)/64;
  const int gO   =(NN+31)/32;
  const int gE   =(ETOT+255)/256;
  const int gN   =(NN+255)/256;
  const int gAGG =(NN*32+255)/256;   // warp per node

  // dense stage 1 + CSR build (CSR independent of features)
  k_in<<<NN/16,128>>>(x,w_in,b_in,g1,be1);
  k_zero_cnt<<<gN,256>>>();
  k_hist<<<gE,256>>>(ei);
  k_scan1<<<SCAN_B,SCAN_T>>>();
  k_scan2<<<1,SCAN_B>>>();
  k_scan3<<<SCAN_B,SCAN_T>>>();
  k_scatter<<<gE,256>>>(ei);

  // ---- GAT layer 1 (fused agg + LN + gelu)
  k_hw<<<gHW,256,shw>>>(W1,as1,ad1);
  k_agg<true><<<gAGG,256>>>(bg1,g2,be2);

  // ---- GAT layer 2
  k_hw<<<gHW,256,shw>>>(W2,as2,ad2);
  k_agg<false><<<gAGG,256>>>(nullptr,nullptr,nullptr);

  k_out<<<gO,128>>>(bg2,w_out,b_out,out);
}

// round 15
// speedup vs baseline: 1.0489x; 1.0400x over previous
#include <cuda_runtime.h>
#include <math.h>

#define NN   50000
#define EE   1600000
#define ETOT (EE+NN)
#define IND  64
#define HID  128
#define NH   4
#define HD   32
#define OUTD 64
#define EPS  1e-5f

#define SCAN_B 128   // phase-1 blocks
#define SCAN_T 256   // phase-1 threads/block (each thread: 2 counts)

// ---------------- scratch (device globals; no allocation allowed) ----------
__device__ __align__(16) float    g_h  [NN*HID];   // activations between stages
__device__ __align__(16) float    g_hW [NN*HID];   // h @ W per GAT layer
__device__ __align__(16) float    g_agg[NN*HID];   // normalized aggregation (layer2)
__device__ __align__(16) float4   g_es [NN];       // per-node per-head src score
__device__ __align__(16) float4   g_ed [NN];       // per-node per-head dst score
__device__ int g_cnt   [NN];                       // CSR: per-dst degree
__device__ int g_rowptr[NN+1];                     // CSR: row pointers
__device__ int g_pos   [NN];                       // CSR: scatter cursors
__device__ int g_csrc  [ETOT];                     // CSR: src id per slot
__device__ int g_tpre  [SCAN_B*SCAN_T];            // scan: per-thread prefix
__device__ int g_bsum  [SCAN_B];                   // scan: block totals
__device__ int g_bbase [SCAN_B];                   // scan: block bases

// ---------------- helpers --------------------------------------------------
__device__ __forceinline__ float gelu_f(float x){
  return 0.5f*x*(1.f+tanhf(0.7978845608028654f*(x+0.044715f*x*x*x)));
}
__device__ __forceinline__ float lrelu(float x){ return x>0.f ? x : 0.2f*x; }
__device__ __forceinline__ int clampN(int v){
  return v<0?0:(v>=NN?NN-1:v);
}

// ---------------- stage 1: h = gelu(LN(x @ w_in + b_in)) -------------------
__global__ void __launch_bounds__(128) k_in(
    const float* __restrict__ x, const float* __restrict__ w,
    const float* __restrict__ b, const float* __restrict__ gam,
    const float* __restrict__ bet)
{
  __shared__ float ws[IND*HID];   // 32 KB
  __shared__ float xs[16*IND];    //  4 KB
  __shared__ float hb[16*HID];    //  8 KB
  const int t = threadIdx.x;
  const int row0 = blockIdx.x*16;   // 50000/16 = 3125 exact

  for(int i=t;i<IND*HID;i+=128) ws[i]=w[i];
  for(int i=t;i<16*IND;i+=128)  xs[i]=x[row0*IND+i];
  __syncthreads();

  const int cg=t&31, rg=t>>5;
  float4 bb=*(const float4*)&b[4*cg];
  float acc[4][4];
  #pragma unroll
  for(int r=0;r<4;r++){acc[r][0]=bb.x;acc[r][1]=bb.y;acc[r][2]=bb.z;acc[r][3]=bb.w;}

  for(int k=0;k<IND;k++){
    float4 wv=*(float4*)&ws[k*HID+4*cg];
    #pragma unroll
    for(int r=0;r<4;r++){
      float hv=xs[(rg*4+r)*IND+k];
      acc[r][0]+=hv*wv.x; acc[r][1]+=hv*wv.y; acc[r][2]+=hv*wv.z; acc[r][3]+=hv*wv.w;
    }
  }
  #pragma unroll
  for(int r=0;r<4;r++)
    *(float4*)&hb[(rg*4+r)*HID+4*cg]=make_float4(acc[r][0],acc[r][1],acc[r][2],acc[r][3]);
  __syncthreads();

  const int lane=t&31, wid=t>>5;
  float4 gg=*(const float4*)&gam[lane*4];
  float4 b2=*(const float4*)&bet[lane*4];
  for(int r=wid;r<16;r+=4){
    float4 v=*(float4*)&hb[r*HID+lane*4];
    float s=v.x+v.y+v.z+v.w;
    float q=v.x*v.x+v.y*v.y+v.z*v.z+v.w*v.w;
    #pragma unroll
    for(int o=16;o;o>>=1){
      s+=__shfl_xor_sync(0xffffffffu,s,o);
      q+=__shfl_xor_sync(0xffffffffu,q,o);
    }
    float mu=s*(1.f/HID);
    float rs=rsqrtf(q*(1.f/HID)-mu*mu+EPS);
    v.x=gelu_f((v.x-mu)*rs*gg.x+b2.x);
    v.y=gelu_f((v.y-mu)*rs*gg.y+b2.y);
    v.z=gelu_f((v.z-mu)*rs*gg.z+b2.z);
    v.w=gelu_f((v.w-mu)*rs*gg.w+b2.w);
    *(float4*)&g_h[(row0+r)*HID+lane*4]=v;
  }
}

// ---------------- stage 2: hW = h @ W ; e_src/e_dst ------------------------
// 256 threads, 64 rows/block, W streamed in two 64-row k-chunks.
__global__ void __launch_bounds__(256) k_hw(
    const float* __restrict__ W, const float* __restrict__ asrc,
    const float* __restrict__ adst)
{
  extern __shared__ float sm[];
  float* Wc  = sm;                 // 64x128 chunk of W (32 KB)
  float* hs  = sm + 64*HID;        // 64x128 inputs   (32 KB)
  float* hwb = hs + 64*HID;        // 64x128 outputs  (32 KB)
  const int t = threadIdx.x;
  const int row0 = blockIdx.x*64;
  const int nrows = min(64, NN-row0);

  for(int i=t;i<nrows*HID;i+=256) hs[i]=g_h[row0*HID+i];
  for(int i=nrows*HID+t;i<64*HID;i+=256) hs[i]=0.f;

  const int cg=t&31, rg=t>>5;      // cols 4*cg.., rows rg*8..rg*8+7
  float acc[8][4];
  #pragma unroll
  for(int r=0;r<8;r++){acc[r][0]=0;acc[r][1]=0;acc[r][2]=0;acc[r][3]=0;}

  for(int kc=0;kc<2;kc++){
    __syncthreads();
    for(int i=t;i<64*HID;i+=256) Wc[i]=W[kc*64*HID+i];
    __syncthreads();
    #pragma unroll 4
    for(int k=0;k<64;k++){
      float4 wv=*(float4*)&Wc[k*HID+4*cg];
      #pragma unroll
      for(int r=0;r<8;r++){
        float hv=hs[(rg*8+r)*HID+kc*64+k];
        acc[r][0]+=hv*wv.x; acc[r][1]+=hv*wv.y; acc[r][2]+=hv*wv.z; acc[r][3]+=hv*wv.w;
      }
    }
  }
  __syncthreads();
  #pragma unroll
  for(int r=0;r<8;r++)
    *(float4*)&hwb[(rg*8+r)*HID+4*cg]=make_float4(acc[r][0],acc[r][1],acc[r][2],acc[r][3]);
  __syncthreads();

  for(int i=t;i<nrows*HID;i+=256) g_hW[row0*HID+i]=hwb[i];

  // attention scores: warp per row (8 warps cycle over 64 rows)
  const int lane=t&31, wid=t>>5;
  for(int r=wid;r<nrows;r+=8){
    float ps[NH], pd[NH];
    #pragma unroll
    for(int h=0;h<NH;h++){
      float v=hwb[r*HID+h*HD+lane];
      ps[h]=v*asrc[h*HD+lane];
      pd[h]=v*adst[h*HD+lane];
    }
    #pragma unroll
    for(int o=16;o;o>>=1){
      #pragma unroll
      for(int h=0;h<NH;h++){
        ps[h]+=__shfl_xor_sync(0xffffffffu,ps[h],o);
        pd[h]+=__shfl_xor_sync(0xffffffffu,pd[h],o);
      }
    }
    if(lane==0){
      g_es[row0+r]=make_float4(ps[0],ps[1],ps[2],ps[3]);
      g_ed[row0+r]=make_float4(pd[0],pd[1],pd[2],pd[3]);
    }
  }
}

// ---------------- CSR build (once; reused by both layers) ------------------
__global__ void k_zero_cnt(){
  int i=blockIdx.x*blockDim.x+threadIdx.x;
  if(i<NN) g_cnt[i]=0;
}
__global__ void k_hist(const int* __restrict__ ei){
  int i=blockIdx.x*blockDim.x+threadIdx.x;
  if(i>=ETOT) return;
  int d = (i<EE)? clampN(ei[EE+i]) : i-EE;
  atomicAdd(&g_cnt[d],1);
}
// 3-phase device-wide exclusive scan of g_cnt -> g_rowptr/g_pos
__global__ void __launch_bounds__(SCAN_T) k_scan1(){
  __shared__ int sh[SCAN_T];
  const int t=threadIdx.x, b=blockIdx.x;
  const int g=b*SCAN_T+t;
  const int i0=g*2;
  int c0=(i0<NN)? g_cnt[i0]:0;
  int c1=(i0+1<NN)? g_cnt[i0+1]:0;
  sh[t]=c0+c1; __syncthreads();
  for(int off=1;off<SCAN_T;off<<=1){
    int v=(t>=off)? sh[t-off]:0; __syncthreads();
    sh[t]+=v; __syncthreads();
  }
  g_tpre[g]=(t==0)?0:sh[t-1];
  if(t==SCAN_T-1) g_bsum[b]=sh[SCAN_T-1];
}
__global__ void __launch_bounds__(SCAN_B) k_scan2(){
  __shared__ int sh[SCAN_B];
  const int t=threadIdx.x;
  sh[t]=g_bsum[t]; __syncthreads();
  for(int off=1;off<SCAN_B;off<<=1){
    int v=(t>=off)? sh[t-off]:0; __syncthreads();
    sh[t]+=v; __syncthreads();
  }
  g_bbase[t]=(t==0)?0:sh[t-1];
}
__global__ void __launch_bounds__(SCAN_T) k_scan3(){
  const int t=threadIdx.x, b=blockIdx.x;
  const int g=b*SCAN_T+t;
  const int i0=g*2;
  int base=g_bbase[b]+g_tpre[g];
  if(i0<NN){
    g_rowptr[i0]=base; g_pos[i0]=base;
    int nb=base+g_cnt[i0];
    if(i0+1<NN){ g_rowptr[i0+1]=nb; g_pos[i0+1]=nb; }
  }
  if(g==0) g_rowptr[NN]=ETOT;
}
__global__ void k_scatter(const int* __restrict__ ei){
  int i=blockIdx.x*blockDim.x+threadIdx.x;
  if(i>=ETOT) return;
  int s,d;
  if(i<EE){ s=clampN(ei[i]); d=clampN(ei[EE+i]); } else { s=d=i-EE; }
  int p=atomicAdd(&g_pos[d],1);
  g_csrc[p]=s;
}

// ---------------- fused aggregation: warp per dst node ---------------------
// acc = sum_e exp(lrelu(es[s]+ed[d])) * hW[s]; den = sum_e w; all in regs.
// 4-way unrolled gather loop for MLP. FUSE_LN: +bias+LN+gelu -> g_h.
template<bool FUSE_LN>
__global__ void __launch_bounds__(256) k_agg(
    const float* __restrict__ bg, const float* __restrict__ gam,
    const float* __restrict__ bet)
{
  int node=(blockIdx.x*blockDim.x+threadIdx.x)>>5;
  int lane=threadIdx.x&31;
  if(node>=NN) return;
  const int h=lane>>3;
  const int beg=g_rowptr[node], end=g_rowptr[node+1];
  const float edv=((const float*)g_ed)[node*4+h];

  float4 acc=make_float4(0.f,0.f,0.f,0.f);
  float den=0.f;
  int j=beg;
  for(; j+3<end; j+=4){
    int s0=g_csrc[j],   s1=g_csrc[j+1];
    int s2=g_csrc[j+2], s3=g_csrc[j+3];
    float e0=((const float*)g_es)[s0*4+h];
    float e1=((const float*)g_es)[s1*4+h];
    float e2=((const float*)g_es)[s2*4+h];
    float e3=((const float*)g_es)[s3*4+h];
    float4 v0=*(const float4*)&g_hW[s0*HID+lane*4];
    float4 v1=*(const float4*)&g_hW[s1*HID+lane*4];
    float4 v2=*(const float4*)&g_hW[s2*HID+lane*4];
    float4 v3=*(const float4*)&g_hW[s3*HID+lane*4];
    float w0=__expf(lrelu(e0+edv));
    float w1=__expf(lrelu(e1+edv));
    float w2=__expf(lrelu(e2+edv));
    float w3=__expf(lrelu(e3+edv));
    acc.x+=w0*v0.x+w1*v1.x+w2*v2.x+w3*v3.x;
    acc.y+=w0*v0.y+w1*v1.y+w2*v2.y+w3*v3.y;
    acc.z+=w0*v0.z+w1*v1.z+w2*v2.z+w3*v3.z;
    acc.w+=w0*v0.w+w1*v1.w+w2*v2.w+w3*v3.w;
    den+=(w0+w1)+(w2+w3);
  }
  for(; j<end; j++){
    int s=g_csrc[j];
    float w=__expf(lrelu(((const float*)g_es)[s*4+h]+edv));
    float4 v=*(const float4*)&g_hW[s*HID+lane*4];
    acc.x+=w*v.x; acc.y+=w*v.y; acc.z+=w*v.z; acc.w+=w*v.w;
    den+=w;
  }
  float inv=1.f/den;
  float4 v;
  v.x=acc.x*inv; v.y=acc.y*inv; v.z=acc.z*inv; v.w=acc.w*inv;

  if(FUSE_LN){
    float4 b4=*(const float4*)&bg[lane*4];
    v.x+=b4.x; v.y+=b4.y; v.z+=b4.z; v.w+=b4.w;
    float s=v.x+v.y+v.z+v.w;
    float q=v.x*v.x+v.y*v.y+v.z*v.z+v.w*v.w;
    #pragma unroll
    for(int o=16;o;o>>=1){
      s+=__shfl_xor_sync(0xffffffffu,s,o);
      q+=__shfl_xor_sync(0xffffffffu,q,o);
    }
    float mu=s*(1.f/HID);
    float rs=rsqrtf(q*(1.f/HID)-mu*mu+EPS);
    float4 gg=*(const float4*)&gam[lane*4];
    float4 b2=*(const float4*)&bet[lane*4];
    v.x=gelu_f((v.x-mu)*rs*gg.x+b2.x);
    v.y=gelu_f((v.y-mu)*rs*gg.y+b2.y);
    v.z=gelu_f((v.z-mu)*rs*gg.z+b2.z);
    v.w=gelu_f((v.w-mu)*rs*gg.w+b2.w);
    *(float4*)&g_h[node*HID+lane*4]=v;
  }else{
    *(float4*)&g_agg[node*HID+lane*4]=v;
  }
}

// ---------------- final: out = (agg + bg2) @ w_out + b_out -----------------
__global__ void __launch_bounds__(128) k_out(
    const float* __restrict__ bg, const float* __restrict__ w,
    const float* __restrict__ bo, float* __restrict__ out)
{
  __shared__ float ws[HID*OUTD];  // 32 KB
  __shared__ float hs[32*HID];    // 16 KB
  const int t=threadIdx.x;
  const int row0=blockIdx.x*32;
  const int nrows=min(32, NN-row0);

  for(int i=t;i<HID*OUTD;i+=128) ws[i]=w[i];
  for(int i=t;i<32*HID;i+=128){
    int r=i>>7, c=i&127;
    hs[i]=(r<nrows)? g_agg[row0*HID+i]+bg[c] : 0.f;
  }
  __syncthreads();

  const int cg=t&15, rg=t>>4;
  float acc[4][4];
  #pragma unroll
  for(int r=0;r<4;r++){acc[r][0]=0;acc[r][1]=0;acc[r][2]=0;acc[r][3]=0;}

  for(int k=0;k<HID;k++){
    float4 wv=*(float4*)&ws[k*OUTD+4*cg];
    #pragma unroll
    for(int r=0;r<4;r++){
      float hv=hs[(rg*4+r)*HID+k];
      acc[r][0]+=hv*wv.x; acc[r][1]+=hv*wv.y; acc[r][2]+=hv*wv.z; acc[r][3]+=hv*wv.w;
    }
  }
  float4 b4=*(const float4*)&bo[4*cg];
  #pragma unroll
  for(int r=0;r<4;r++){
    int row=row0+rg*4+r;
    if(row<NN)
      *(float4*)&out[row*OUTD+4*cg]=
        make_float4(acc[r][0]+b4.x,acc[r][1]+b4.y,acc[r][2]+b4.z,acc[r][3]+b4.w);
  }
}

// ---------------- launch ----------------------------------------------------
extern "C" void kernel_launch(void* const* d_in, const int* in_sizes, int n_in,
                              void* d_out, int out_size)
{
  const float* x    =(const float*)d_in[0];
  const int*   ei   =(const int*)d_in[1];
  const float* w_in =(const float*)d_in[2];
  const float* b_in =(const float*)d_in[3];
  const float* g1   =(const float*)d_in[4];
  const float* be1  =(const float*)d_in[5];
  const float* W1   =(const float*)d_in[6];
  const float* as1  =(const float*)d_in[7];
  const float* ad1  =(const float*)d_in[8];
  const float* bg1  =(const float*)d_in[9];
  const float* g2   =(const float*)d_in[10];
  const float* be2  =(const float*)d_in[11];
  const float* W2   =(const float*)d_in[12];
  const float* as2  =(const float*)d_in[13];
  const float* ad2  =(const float*)d_in[14];
  const float* bg2  =(const float*)d_in[15];
  const float* w_out=(const float*)d_in[16];
  const float* b_out=(const float*)d_in[17];
  float* out=(float*)d_out;

  const size_t shw=(64*HID*3)*sizeof(float); // 96 KB
  cudaFuncSetAttribute(k_hw, cudaFuncAttributeMaxDynamicSharedMemorySize,(int)shw);

  const int gHW  =(NN+63)/64;
  const int gO   =(NN+31)/32;
  const int gE   =(ETOT+255)/256;
  const int gN   =(NN+255)/256;
  const int gAGG =(NN*32+255)/256;   // warp per node

  // Fork a side stream for the CSR build (independent of k_in/k_hw):
  // standard event-based fork/join so CUDA-graph capture records a
  // parallel branch. Streams/events are host objects (no device alloc),
  // created and destroyed every call -> fully deterministic.
  cudaStream_t s2;
  cudaEvent_t eFork, eJoin;
  cudaStreamCreateWithFlags(&s2, cudaStreamNonBlocking);
  cudaEventCreateWithFlags(&eFork, cudaEventDisableTiming);
  cudaEventCreateWithFlags(&eJoin, cudaEventDisableTiming);

  cudaEventRecord(eFork, 0);
  cudaStreamWaitEvent(s2, eFork, 0);

  // ---- branch B (s2): CSR build
  k_zero_cnt<<<gN,256,0,s2>>>();
  k_hist<<<gE,256,0,s2>>>(ei);
  k_scan1<<<SCAN_B,SCAN_T,0,s2>>>();
  k_scan2<<<1,SCAN_B,0,s2>>>();
  k_scan3<<<SCAN_B,SCAN_T,0,s2>>>();
  k_scatter<<<gE,256,0,s2>>>(ei);
  cudaEventRecord(eJoin, s2);

  // ---- branch A (main stream): dense front-end
  k_in<<<NN/16,128>>>(x,w_in,b_in,g1,be1);
  k_hw<<<gHW,256,shw>>>(W1,as1,ad1);

  // join: aggregation needs both hW/scores and the CSR
  cudaStreamWaitEvent(0, eJoin, 0);

  // ---- GAT layer 1 (fused agg + LN + gelu)
  k_agg<true><<<gAGG,256>>>(bg1,g2,be2);

  // ---- GAT layer 2
  k_hw<<<gHW,256,shw>>>(W2,as2,ad2);
  k_agg<false><<<gAGG,256>>>(nullptr,nullptr,nullptr);

  k_out<<<gO,128>>>(bg2,w_out,b_out,out);

  cudaStreamDestroy(s2);
  cudaEventDestroy(eFork);
  cudaEventDestroy(eJoin);
}

// round 16
// speedup vs baseline: 1.0983x; 1.0471x over previous
#include <cuda_runtime.h>
#include <math.h>

#define NN   50000
#define EE   1600000
#define ETOT (EE+NN)
#define IND  64
#define HID  128
#define NH   4
#define HD   32
#define OUTD 64
#define EPS  1e-5f

#define SCAN_B 128   // phase-1 blocks
#define SCAN_T 256   // phase-1 threads/block (each thread: 2 counts)

// ---------------- scratch (device globals; no allocation allowed) ----------
__device__ __align__(16) float    g_h  [NN*HID];   // activations between stages
__device__ __align__(16) float    g_hW [NN*HID];   // h @ W per GAT layer
__device__ __align__(16) float    g_agg[NN*HID];   // normalized aggregation (layer2)
__device__ __align__(16) float4   g_es [NN];       // per-node per-head src score
__device__ __align__(16) float4   g_ed [NN];       // per-node per-head dst score
__device__ int g_cnt   [NN];                       // CSR: per-dst degree
__device__ int g_rowptr[NN+1];                     // CSR: row pointers
__device__ int g_pos   [NN];                       // CSR: scatter cursors
__device__ int g_csrc  [ETOT];                     // CSR: src id per slot
__device__ int g_tpre  [SCAN_B*SCAN_T];            // scan: per-thread prefix
__device__ int g_bsum  [SCAN_B];                   // scan: block totals
__device__ int g_bbase [SCAN_B];                   // scan: block bases

// ---------------- helpers --------------------------------------------------
__device__ __forceinline__ float gelu_f(float x){
  return 0.5f*x*(1.f+tanhf(0.7978845608028654f*(x+0.044715f*x*x*x)));
}
__device__ __forceinline__ float lrelu(float x){ return x>0.f ? x : 0.2f*x; }
__device__ __forceinline__ int clampN(int v){
  return v<0?0:(v>=NN?NN-1:v);
}

// ---------------- stage 1: h = gelu(LN(x @ w_in + b_in)) -------------------
// 256 threads, 64 rows/block, 8-row x 4-col register tile (same as k_hw).
__global__ void __launch_bounds__(256) k_in(
    const float* __restrict__ x, const float* __restrict__ w,
    const float* __restrict__ b, const float* __restrict__ gam,
    const float* __restrict__ bet)
{
  extern __shared__ float sm[];
  float* ws = sm;                  // 64x128 W (32 KB)
  float* xs = sm + IND*HID;        // 64x64 inputs (16 KB)
  float* hb = xs + 64*IND;         // 64x128 outputs (32 KB)
  const int t = threadIdx.x;
  const int row0 = blockIdx.x*64;
  const int nrows = min(64, NN-row0);

  for(int i=t;i<IND*HID;i+=256) ws[i]=w[i];
  for(int i=t;i<nrows*IND;i+=256) xs[i]=x[row0*IND+i];
  for(int i=nrows*IND+t;i<64*IND;i+=256) xs[i]=0.f;
  __syncthreads();

  const int cg=t&31, rg=t>>5;       // cols 4*cg.., rows rg*8..rg*8+7
  float4 bb=*(const float4*)&b[4*cg];
  float acc[8][4];
  #pragma unroll
  for(int r=0;r<8;r++){acc[r][0]=bb.x;acc[r][1]=bb.y;acc[r][2]=bb.z;acc[r][3]=bb.w;}

  #pragma unroll 4
  for(int k=0;k<IND;k++){
    float4 wv=*(float4*)&ws[k*HID+4*cg];
    #pragma unroll
    for(int r=0;r<8;r++){
      float hv=xs[(rg*8+r)*IND+k];
      acc[r][0]+=hv*wv.x; acc[r][1]+=hv*wv.y; acc[r][2]+=hv*wv.z; acc[r][3]+=hv*wv.w;
    }
  }
  #pragma unroll
  for(int r=0;r<8;r++)
    *(float4*)&hb[(rg*8+r)*HID+4*cg]=make_float4(acc[r][0],acc[r][1],acc[r][2],acc[r][3]);
  __syncthreads();

  // LN + gelu: warp per row (8 warps cycle over rows)
  const int lane=t&31, wid=t>>5;
  float4 gg=*(const float4*)&gam[lane*4];
  float4 b2=*(const float4*)&bet[lane*4];
  for(int r=wid;r<nrows;r+=8){
    float4 v=*(float4*)&hb[r*HID+lane*4];
    float s=v.x+v.y+v.z+v.w;
    float q=v.x*v.x+v.y*v.y+v.z*v.z+v.w*v.w;
    #pragma unroll
    for(int o=16;o;o>>=1){
      s+=__shfl_xor_sync(0xffffffffu,s,o);
      q+=__shfl_xor_sync(0xffffffffu,q,o);
    }
    float mu=s*(1.f/HID);
    float rs=rsqrtf(q*(1.f/HID)-mu*mu+EPS);
    v.x=gelu_f((v.x-mu)*rs*gg.x+b2.x);
    v.y=gelu_f((v.y-mu)*rs*gg.y+b2.y);
    v.z=gelu_f((v.z-mu)*rs*gg.z+b2.z);
    v.w=gelu_f((v.w-mu)*rs*gg.w+b2.w);
    *(float4*)&g_h[(row0+r)*HID+lane*4]=v;
  }
}

// ---------------- stage 2: hW = h @ W ; e_src/e_dst ------------------------
// 256 threads, 64 rows/block, W streamed in two 64-row k-chunks.
__global__ void __launch_bounds__(256) k_hw(
    const float* __restrict__ W, const float* __restrict__ asrc,
    const float* __restrict__ adst)
{
  extern __shared__ float sm[];
  float* Wc  = sm;                 // 64x128 chunk of W (32 KB)
  float* hs  = sm + 64*HID;        // 64x128 inputs   (32 KB)
  float* hwb = hs + 64*HID;        // 64x128 outputs  (32 KB)
  const int t = threadIdx.x;
  const int row0 = blockIdx.x*64;
  const int nrows = min(64, NN-row0);

  for(int i=t;i<nrows*HID;i+=256) hs[i]=g_h[row0*HID+i];
  for(int i=nrows*HID+t;i<64*HID;i+=256) hs[i]=0.f;

  const int cg=t&31, rg=t>>5;      // cols 4*cg.., rows rg*8..rg*8+7
  float acc[8][4];
  #pragma unroll
  for(int r=0;r<8;r++){acc[r][0]=0;acc[r][1]=0;acc[r][2]=0;acc[r][3]=0;}

  for(int kc=0;kc<2;kc++){
    __syncthreads();
    for(int i=t;i<64*HID;i+=256) Wc[i]=W[kc*64*HID+i];
    __syncthreads();
    #pragma unroll 4
    for(int k=0;k<64;k++){
      float4 wv=*(float4*)&Wc[k*HID+4*cg];
      #pragma unroll
      for(int r=0;r<8;r++){
        float hv=hs[(rg*8+r)*HID+kc*64+k];
        acc[r][0]+=hv*wv.x; acc[r][1]+=hv*wv.y; acc[r][2]+=hv*wv.z; acc[r][3]+=hv*wv.w;
      }
    }
  }
  __syncthreads();
  #pragma unroll
  for(int r=0;r<8;r++)
    *(float4*)&hwb[(rg*8+r)*HID+4*cg]=make_float4(acc[r][0],acc[r][1],acc[r][2],acc[r][3]);
  __syncthreads();

  for(int i=t;i<nrows*HID;i+=256) g_hW[row0*HID+i]=hwb[i];

  // attention scores: warp per row (8 warps cycle over 64 rows)
  const int lane=t&31, wid=t>>5;
  for(int r=wid;r<nrows;r+=8){
    float ps[NH], pd[NH];
    #pragma unroll
    for(int h=0;h<NH;h++){
      float v=hwb[r*HID+h*HD+lane];
      ps[h]=v*asrc[h*HD+lane];
      pd[h]=v*adst[h*HD+lane];
    }
    #pragma unroll
    for(int o=16;o;o>>=1){
      #pragma unroll
      for(int h=0;h<NH;h++){
        ps[h]+=__shfl_xor_sync(0xffffffffu,ps[h],o);
        pd[h]+=__shfl_xor_sync(0xffffffffu,pd[h],o);
      }
    }
    if(lane==0){
      g_es[row0+r]=make_float4(ps[0],ps[1],ps[2],ps[3]);
      g_ed[row0+r]=make_float4(pd[0],pd[1],pd[2],pd[3]);
    }
  }
}

// ---------------- CSR build (once; reused by both layers) ------------------
__global__ void k_zero_cnt(){
  int i=blockIdx.x*blockDim.x+threadIdx.x;
  if(i<NN) g_cnt[i]=0;
}
__global__ void k_hist(const int* __restrict__ ei){
  int i=blockIdx.x*blockDim.x+threadIdx.x;
  if(i>=ETOT) return;
  int d = (i<EE)? clampN(ei[EE+i]) : i-EE;
  atomicAdd(&g_cnt[d],1);
}
// 3-phase device-wide exclusive scan of g_cnt -> g_rowptr/g_pos
__global__ void __launch_bounds__(SCAN_T) k_scan1(){
  __shared__ int sh[SCAN_T];
  const int t=threadIdx.x, b=blockIdx.x;
  const int g=b*SCAN_T+t;
  const int i0=g*2;
  int c0=(i0<NN)? g_cnt[i0]:0;
  int c1=(i0+1<NN)? g_cnt[i0+1]:0;
  sh[t]=c0+c1; __syncthreads();
  for(int off=1;off<SCAN_T;off<<=1){
    int v=(t>=off)? sh[t-off]:0; __syncthreads();
    sh[t]+=v; __syncthreads();
  }
  g_tpre[g]=(t==0)?0:sh[t-1];
  if(t==SCAN_T-1) g_bsum[b]=sh[SCAN_T-1];
}
__global__ void __launch_bounds__(SCAN_B) k_scan2(){
  __shared__ int sh[SCAN_B];
  const int t=threadIdx.x;
  sh[t]=g_bsum[t]; __syncthreads();
  for(int off=1;off<SCAN_B;off<<=1){
    int v=(t>=off)? sh[t-off]:0; __syncthreads();
    sh[t]+=v; __syncthreads();
  }
  g_bbase[t]=(t==0)?0:sh[t-1];
}
__global__ void __launch_bounds__(SCAN_T) k_scan3(){
  const int t=threadIdx.x, b=blockIdx.x;
  const int g=b*SCAN_T+t;
  const int i0=g*2;
  int base=g_bbase[b]+g_tpre[g];
  if(i0<NN){
    g_rowptr[i0]=base; g_pos[i0]=base;
    int nb=base+g_cnt[i0];
    if(i0+1<NN){ g_rowptr[i0+1]=nb; g_pos[i0+1]=nb; }
  }
  if(g==0) g_rowptr[NN]=ETOT;
}
__global__ void k_scatter(const int* __restrict__ ei){
  int i=blockIdx.x*blockDim.x+threadIdx.x;
  if(i>=ETOT) return;
  int s,d;
  if(i<EE){ s=clampN(ei[i]); d=clampN(ei[EE+i]); } else { s=d=i-EE; }
  int p=atomicAdd(&g_pos[d],1);
  g_csrc[p]=s;
}

// ---------------- fused aggregation: warp per dst node ---------------------
// acc = sum_e exp(lrelu(es[s]+ed[d])) * hW[s]; den = sum_e w; all in regs.
// 8-way unrolled gather loop for MLP. FUSE_LN: +bias+LN+gelu -> g_h.
template<bool FUSE_LN>
__global__ void __launch_bounds__(256) k_agg(
    const float* __restrict__ bg, const float* __restrict__ gam,
    const float* __restrict__ bet)
{
  int node=(blockIdx.x*blockDim.x+threadIdx.x)>>5;
  int lane=threadIdx.x&31;
  if(node>=NN) return;
  const int h=lane>>3;
  const int beg=g_rowptr[node], end=g_rowptr[node+1];
  const float edv=((const float*)g_ed)[node*4+h];

  float4 acc=make_float4(0.f,0.f,0.f,0.f);
  float den=0.f;
  int j=beg;
  for(; j+7<end; j+=8){
    int s[8]; float e[8]; float4 v[8]; float w[8];
    #pragma unroll
    for(int u=0;u<8;u++) s[u]=g_csrc[j+u];
    #pragma unroll
    for(int u=0;u<8;u++) e[u]=((const float*)g_es)[s[u]*4+h];
    #pragma unroll
    for(int u=0;u<8;u++) v[u]=*(const float4*)&g_hW[s[u]*HID+lane*4];
    #pragma unroll
    for(int u=0;u<8;u++) w[u]=__expf(lrelu(e[u]+edv));
    #pragma unroll
    for(int u=0;u<8;u++){
      acc.x+=w[u]*v[u].x; acc.y+=w[u]*v[u].y;
      acc.z+=w[u]*v[u].z; acc.w+=w[u]*v[u].w;
      den+=w[u];
    }
  }
  for(; j<end; j++){
    int s=g_csrc[j];
    float w=__expf(lrelu(((const float*)g_es)[s*4+h]+edv));
    float4 v=*(const float4*)&g_hW[s*HID+lane*4];
    acc.x+=w*v.x; acc.y+=w*v.y; acc.z+=w*v.z; acc.w+=w*v.w;
    den+=w;
  }
  float inv=1.f/den;
  float4 v;
  v.x=acc.x*inv; v.y=acc.y*inv; v.z=acc.z*inv; v.w=acc.w*inv;

  if(FUSE_LN){
    float4 b4=*(const float4*)&bg[lane*4];
    v.x+=b4.x; v.y+=b4.y; v.z+=b4.z; v.w+=b4.w;
    float s=v.x+v.y+v.z+v.w;
    float q=v.x*v.x+v.y*v.y+v.z*v.z+v.w*v.w;
    #pragma unroll
    for(int o=16;o;o>>=1){
      s+=__shfl_xor_sync(0xffffffffu,s,o);
      q+=__shfl_xor_sync(0xffffffffu,q,o);
    }
    float mu=s*(1.f/HID);
    float rs=rsqrtf(q*(1.f/HID)-mu*mu+EPS);
    float4 gg=*(const float4*)&gam[lane*4];
    float4 b2=*(const float4*)&bet[lane*4];
    v.x=gelu_f((v.x-mu)*rs*gg.x+b2.x);
    v.y=gelu_f((v.y-mu)*rs*gg.y+b2.y);
    v.z=gelu_f((v.z-mu)*rs*gg.z+b2.z);
    v.w=gelu_f((v.w-mu)*rs*gg.w+b2.w);
    *(float4*)&g_h[node*HID+lane*4]=v;
  }else{
    *(float4*)&g_agg[node*HID+lane*4]=v;
  }
}

// ---------------- final: out = (agg + bg2) @ w_out + b_out -----------------
__global__ void __launch_bounds__(128) k_out(
    const float* __restrict__ bg, const float* __restrict__ w,
    const float* __restrict__ bo, float* __restrict__ out)
{
  __shared__ float ws[HID*OUTD];  // 32 KB
  __shared__ float hs[32*HID];    // 16 KB
  const int t=threadIdx.x;
  const int row0=blockIdx.x*32;
  const int nrows=min(32, NN-row0);

  for(int i=t;i<HID*OUTD;i+=128) ws[i]=w[i];
  for(int i=t;i<32*HID;i+=128){
    int r=i>>7, c=i&127;
    hs[i]=(r<nrows)? g_agg[row0*HID+i]+bg[c] : 0.f;
  }
  __syncthreads();

  const int cg=t&15, rg=t>>4;
  float acc[4][4];
  #pragma unroll
  for(int r=0;r<4;r++){acc[r][0]=0;acc[r][1]=0;acc[r][2]=0;acc[r][3]=0;}

  for(int k=0;k<HID;k++){
    float4 wv=*(float4*)&ws[k*OUTD+4*cg];
    #pragma unroll
    for(int r=0;r<4;r++){
      float hv=hs[(rg*4+r)*HID+k];
      acc[r][0]+=hv*wv.x; acc[r][1]+=hv*wv.y; acc[r][2]+=hv*wv.z; acc[r][3]+=hv*wv.w;
    }
  }
  float4 b4=*(const float4*)&bo[4*cg];
  #pragma unroll
  for(int r=0;r<4;r++){
    int row=row0+rg*4+r;
    if(row<NN)
      *(float4*)&out[row*OUTD+4*cg]=
        make_float4(acc[r][0]+b4.x,acc[r][1]+b4.y,acc[r][2]+b4.z,acc[r][3]+b4.w);
  }
}

// ---------------- launch ----------------------------------------------------
extern "C" void kernel_launch(void* const* d_in, const int* in_sizes, int n_in,
                              void* d_out, int out_size)
{
  const float* x    =(const float*)d_in[0];
  const int*   ei   =(const int*)d_in[1];
  const float* w_in =(const float*)d_in[2];
  const float* b_in =(const float*)d_in[3];
  const float* g1   =(const float*)d_in[4];
  const float* be1  =(const float*)d_in[5];
  const float* W1   =(const float*)d_in[6];
  const float* as1  =(const float*)d_in[7];
  const float* ad1  =(const float*)d_in[8];
  const float* bg1  =(const float*)d_in[9];
  const float* g2   =(const float*)d_in[10];
  const float* be2  =(const float*)d_in[11];
  const float* W2   =(const float*)d_in[12];
  const float* as2  =(const float*)d_in[13];
  const float* ad2  =(const float*)d_in[14];
  const float* bg2  =(const float*)d_in[15];
  const float* w_out=(const float*)d_in[16];
  const float* b_out=(const float*)d_in[17];
  float* out=(float*)d_out;

  const size_t shw=(64*HID*3)*sizeof(float);                 // 96 KB (k_hw)
  const size_t shin=(IND*HID+64*IND+64*HID)*sizeof(float);   // 80 KB (k_in)
  cudaFuncSetAttribute(k_hw, cudaFuncAttributeMaxDynamicSharedMemorySize,(int)shw);
  cudaFuncSetAttribute(k_in, cudaFuncAttributeMaxDynamicSharedMemorySize,(int)shin);

  const int gHW  =(NN+63)/64;
  const int gO   =(NN+31)/32;
  const int gE   =(ETOT+255)/256;
  const int gN   =(NN+255)/256;
  const int gAGG =(NN*32+255)/256;   // warp per node

  // Fork a side stream for the CSR build (independent of k_in/k_hw).
  cudaStream_t s2;
  cudaEvent_t eFork, eJoin;
  cudaStreamCreateWithFlags(&s2, cudaStreamNonBlocking);
  cudaEventCreateWithFlags(&eFork, cudaEventDisableTiming);
  cudaEventCreateWithFlags(&eJoin, cudaEventDisableTiming);

  cudaEventRecord(eFork, 0);
  cudaStreamWaitEvent(s2, eFork, 0);

  // ---- branch B (s2): CSR build
  k_zero_cnt<<<gN,256,0,s2>>>();
  k_hist<<<gE,256,0,s2>>>(ei);
  k_scan1<<<SCAN_B,SCAN_T,0,s2>>>();
  k_scan2<<<1,SCAN_B,0,s2>>>();
  k_scan3<<<SCAN_B,SCAN_T,0,s2>>>();
  k_scatter<<<gE,256,0,s2>>>(ei);
  cudaEventRecord(eJoin, s2);

  // ---- branch A (main stream): dense front-end
  k_in<<<gHW,256,shin>>>(x,w_in,b_in,g1,be1);
  k_hw<<<gHW,256,shw>>>(W1,as1,ad1);

  // join: aggregation needs both hW/scores and the CSR
  cudaStreamWaitEvent(0, eJoin, 0);

  // ---- GAT layer 1 (fused agg + LN + gelu)
  k_agg<true><<<gAGG,256>>>(bg1,g2,be2);

  // ---- GAT layer 2
  k_hw<<<gHW,256,shw>>>(W2,as2,ad2);
  k_agg<false><<<gAGG,256>>>(nullptr,nullptr,nullptr);

  k_out<<<gO,128>>>(bg2,w_out,b_out,out);

  cudaStreamDestroy(s2);
  cudaEventDestroy(eFork);
  cudaEventDestroy(eJoin);
}